// round 8
// baseline (speedup 1.0000x reference)
#include <cuda_runtime.h>

#define NB   256   // batch
#define HD   1024  // hidden
#define NOBS 256   // obs dim
#define NA   18    // actions
#define SPLIT 4

// Scratch (allocation-free rule: __device__ globals). Ping-pong partial buffers.
__device__ float g_pA[SPLIT * NB * HD];
__device__ float g_pB[SPLIT * NB * HD];

enum { M_FMA = 0, M_MAX = 1, M_MIN = 2 };          // reduction semiring
enum { C_NONE = 0, C_SUM_BIAS = 1, C_MAX = 2 };    // inline combine of producer's split-K partials

constexpr int BT = 32;       // batch tile
constexpr int OT = 128;      // out tile
constexpr int KC = 64;       // k chunk
constexpr int NT = 256;      // threads
constexpr int WST = OT + 4;  // padded smem strides (kill STS bank conflicts)
constexpr int HST = BT + 4;

// Load h[b, iabs..iabs+3], combining the producer's SPLIT partial slices inline.
template<int COMB>
__device__ __forceinline__ float4 load_h4(const float* __restrict__ hb,
                                          const float* __restrict__ bias, int iabs)
{
    float4 v = *(const float4*)hb;
    if (COMB != C_NONE) {
#pragma unroll
        for (int s = 1; s < SPLIT; s++) {
            const float4 u = *(const float4*)(hb + s * (NB * HD));
            if (COMB == C_SUM_BIAS) {
                v.x += u.x; v.y += u.y; v.z += u.z; v.w += u.w;
            } else {
                v.x = fmaxf(v.x, u.x); v.y = fmaxf(v.y, u.y);
                v.z = fmaxf(v.z, u.z); v.w = fmaxf(v.w, u.w);
            }
        }
        if (COMB == C_SUM_BIAS) {
            const float4 b = *(const float4*)(bias + iabs);
            v.x += b.x; v.y += b.y; v.z += b.z; v.w += b.w;
        }
    }
    return v;
}

// out[b,o] = red_i op(W[o,i], h[b,i]); split-K partials into part[z][b][o].
// h is materialized on the fly from the producer's partials (COMB).
// __launch_bounds__(NT, 2): force 2 CTAs/SM so all 256 CTAs are co-resident
// (one wave, no 1.73-wave tail imbalance) and 4 warps/SMSP hide LDS/barrier.
template<int MODE, int COMB>
__global__ __launch_bounds__(NT, 2)
void semiring_kernel(const float* __restrict__ Wm,
                     const float* __restrict__ Hin,
                     const float* __restrict__ hbias,
                     float* __restrict__ part,
                     int Kld, int Ki)
{
    __shared__ float sh_w[KC * WST];
    __shared__ float sh_h[KC * HST];

    const int tid = threadIdx.x;
    const int o0  = blockIdx.x * OT;
    const int b0  = blockIdx.y * BT;
    const int i0  = blockIdx.z * Ki;

    const int og = tid & 31;   // o4-group: o = o0 + og*4 + oo
    const int bg = tid >> 5;   // b4-group: b = b0 + bg*4 + bb
    const int lo = tid & 7;    // i4 slot for loads
    const int ro = tid >> 3;   // row slot for loads (0..31)

    const float init = (MODE == M_FMA) ? 0.0f
                     : (MODE == M_MAX) ? -3.402823466e38f : 3.402823466e38f;
    float acc[4][4];
#pragma unroll
    for (int bb = 0; bb < 4; bb++)
#pragma unroll
        for (int oo = 0; oo < 4; oo++) acc[bb][oo] = init;

    const float* wbase = Wm  + (o0 + ro) * Kld + i0 + lo * 4;
    const float* hbase = Hin + (b0 + ro) * Kld + i0 + lo * 4;

    float4 wreg[2][4];
    float4 hreg[2];
    const int nC = Ki / KC;

    // prologue: chunk 0 into regs (two 32-wide halves in i)
#pragma unroll
    for (int s = 0; s < 2; s++) {
#pragma unroll
        for (int r = 0; r < 4; r++)
            wreg[s][r] = *(const float4*)(wbase + r * 32 * Kld + s * 32);
        hreg[s] = load_h4<COMB>(hbase + s * 32, hbias, i0 + s * 32 + lo * 4);
    }

    for (int c = 0; c < nC; c++) {
        // stage regs -> smem, transposed: sh[i_local][col]
#pragma unroll
        for (int s = 0; s < 2; s++) {
            const int ib = s * 32 + lo * 4;
#pragma unroll
            for (int r = 0; r < 4; r++) {
                const int col = r * 32 + ro;
                sh_w[(ib + 0) * WST + col] = wreg[s][r].x;
                sh_w[(ib + 1) * WST + col] = wreg[s][r].y;
                sh_w[(ib + 2) * WST + col] = wreg[s][r].z;
                sh_w[(ib + 3) * WST + col] = wreg[s][r].w;
            }
            sh_h[(ib + 0) * HST + ro] = hreg[s].x;
            sh_h[(ib + 1) * HST + ro] = hreg[s].y;
            sh_h[(ib + 2) * HST + ro] = hreg[s].z;
            sh_h[(ib + 3) * HST + ro] = hreg[s].w;
        }
        __syncthreads();

        // prefetch next chunk (LDG latency overlapped with compute)
        if (c + 1 < nC) {
            const int ic = (c + 1) * KC;
#pragma unroll
            for (int s = 0; s < 2; s++) {
#pragma unroll
                for (int r = 0; r < 4; r++)
                    wreg[s][r] = *(const float4*)(wbase + r * 32 * Kld + ic + s * 32);
                hreg[s] = load_h4<COMB>(hbase + ic + s * 32, hbias,
                                        i0 + ic + s * 32 + lo * 4);
            }
        }

#pragma unroll 4
        for (int i = 0; i < KC; i++) {
            const float4 wv = *(const float4*)&sh_w[i * WST + og * 4]; // conflict-free
            const float4 hv = *(const float4*)&sh_h[i * HST + bg * 4]; // broadcast
            const float w4[4] = {wv.x, wv.y, wv.z, wv.w};
            const float h4[4] = {hv.x, hv.y, hv.z, hv.w};
#pragma unroll
            for (int bb = 0; bb < 4; bb++)
#pragma unroll
                for (int oo = 0; oo < 4; oo++) {
                    if (MODE == M_FMA)
                        acc[bb][oo] = fmaf(w4[oo], h4[bb], acc[bb][oo]);
                    else if (MODE == M_MAX)
                        acc[bb][oo] = fmaxf(acc[bb][oo], w4[oo] + h4[bb]);
                    else
                        acc[bb][oo] = fminf(acc[bb][oo], w4[oo] + h4[bb]);
                }
        }
        __syncthreads();
    }

    float* pout = part + (blockIdx.z * NB + b0 + bg * 4) * HD + o0 + og * 4;
#pragma unroll
    for (int bb = 0; bb < 4; bb++) {
        const float4 v = make_float4(acc[bb][0], acc[bb][1], acc[bb][2], acc[bb][3]);
        *(float4*)(pout + bb * HD) = v;
    }
}

// One CTA per batch row b. Min-combine the SPLIT partials of h3 ONCE into smem
// (each thread owns one float4), then 8 warps compute the 18 dot products.
// Removes the 18x redundant partial re-reads of the old per-(b,a)-warp version.
__global__ __launch_bounds__(256)
void fcout_kernel(const float* __restrict__ hpart, const float* __restrict__ Wout,
                  const float* __restrict__ bout, float* __restrict__ q)
{
    __shared__ float sh[HD];
    const int b    = blockIdx.x;
    const int tid  = threadIdx.x;
    const int wid  = tid >> 5;
    const int lane = tid & 31;

    // h[b, tid*4 .. tid*4+3] = min over SPLIT slices
    const float4* hp = (const float4*)hpart + b * (HD / 4) + tid;
    float4 v = hp[0];
#pragma unroll
    for (int z = 1; z < SPLIT; z++) {
        const float4 u = hp[z * (NB * HD / 4)];
        v.x = fminf(v.x, u.x); v.y = fminf(v.y, u.y);
        v.z = fminf(v.z, u.z); v.w = fminf(v.w, u.w);
    }
    ((float4*)sh)[tid] = v;
    __syncthreads();

    // warp w handles actions a = w, w+8, w+16
    for (int a = wid; a < NA; a += 8) {
        const float4* wr = (const float4*)(Wout + a * HD);
        const float4* hs = (const float4*)sh;
        float s = 0.0f;
#pragma unroll
        for (int k = 0; k < HD / 128; k++) {           // 8 iters of float4
            const float4 w4 = wr[lane + k * 32];
            const float4 h4 = hs[lane + k * 32];
            s = fmaf(w4.x, h4.x, s);
            s = fmaf(w4.y, h4.y, s);
            s = fmaf(w4.z, h4.z, s);
            s = fmaf(w4.w, h4.w, s);
        }
#pragma unroll
        for (int d = 16; d; d >>= 1) s += __shfl_xor_sync(0xffffffffu, s, d);
        if (lane == 0) q[b * NA + a] = s + bout[a];
    }
}

extern "C" void kernel_launch(void* const* d_in, const int* in_sizes, int n_in,
                              void* d_out, int out_size)
{
    const float* x     = (const float*)d_in[0];
    const float* W_in  = (const float*)d_in[1];
    const float* b_in  = (const float*)d_in[2];
    const float* W_max = (const float*)d_in[3];
    const float* W_min = (const float*)d_in[4];
    const float* W_out = (const float*)d_in[5];
    const float* b_out = (const float*)d_in[6];
    float* q = (float*)d_out;

    float *pA, *pB;
    cudaGetSymbolAddress((void**)&pA, g_pA);
    cudaGetSymbolAddress((void**)&pB, g_pB);

    const dim3 grid(HD / OT, NB / BT, SPLIT);  // (8, 8, 4) = 256 CTAs

    // 1) fc_in partials: pA[z] = x @ W_in^T (split over obs dim)
    semiring_kernel<M_FMA, C_NONE><<<grid, NT>>>(W_in, x, nullptr, pA, NOBS, NOBS / SPLIT);

    // 2) max-plus: h1 = sum_z pA + b_in materialized inline; pB[z] = partial max-plus
    semiring_kernel<M_MAX, C_SUM_BIAS><<<grid, NT>>>(W_max, pA, b_in, pB, HD, HD / SPLIT);

    // 3) min-plus: h2 = max_z pB inline; pA[z] = partial min-plus
    semiring_kernel<M_MIN, C_MAX><<<grid, NT>>>(W_min, pB, nullptr, pA, HD, HD / SPLIT);

    // 4) fc_out: h3 = min_z pA inline; q = h3 @ W_out^T + b_out
    fcout_kernel<<<NB, 256>>>(pA, W_out, b_out, q);
}

// round 10
// speedup vs baseline: 1.0556x; 1.0556x over previous
#include <cuda_runtime.h>

#define NB   256   // batch
#define HD   1024  // hidden
#define NOBS 256   // obs dim
#define NA   18    // actions
#define SPLIT 8

// Scratch (allocation-free rule: __device__ globals).
__device__ float g_part[SPLIT * NB * HD];   // split-K partials (8 MB)
__device__ float g_h1[NB * HD];             // combined activations
__device__ float g_h2[NB * HD];

enum { M_FMA = 0, M_MAX = 1, M_MIN = 2 };

constexpr int BT = 64;        // batch tile (8 b per thread — halves smem crossbar B/pair)
constexpr int OT = 128;       // out tile
constexpr int KC = 32;        // k chunk
constexpr int NT = 256;       // threads (8 warps)
constexpr int WST = OT + 4;   // 132
constexpr int HST = BT + 4;   // 68
constexpr int SW_SZ = KC * WST;               // floats per w buffer
constexpr int SH_SZ = KC * HST;               // floats per h buffer
constexpr int SMEM_BYTES = 2 * (SW_SZ + SH_SZ) * 4;  // 51200 B (dynamic; >48K static limit)

// out[b,o] = red_i op(W[o,i], h[b,i]) over i in [i0, i0+Ki); partial per z-slice.
// Double-buffered smem: ONE __syncthreads per chunk. Per-thread tile 8b x 4o.
template<int MODE>
__global__ __launch_bounds__(NT, 2)
void semiring_kernel(const float* __restrict__ Wm, const float* __restrict__ Hin,
                     float* __restrict__ part, int Kld, int Ki)
{
    extern __shared__ float smem[];
    float* sw = smem;                 // [2][KC][WST], transposed: sw[i][o]
    float* sh = smem + 2 * SW_SZ;     // [2][KC][HST], transposed: sh[i][b]

    const int tid = threadIdx.x;
    const int o0  = blockIdx.x * OT;
    const int b0  = blockIdx.y * BT;
    const int i0  = blockIdx.z * Ki;

    const int og = tid & 31;   // lane: o = o0 + og*4 + oo
    const int bg = tid >> 5;   // warp: b = b0 + bg*8 + bb
    const int lo = tid & 7;    // loader i4 slot
    const int ro = tid >> 3;   // loader row slot (0..31)

    const float init = (MODE == M_FMA) ? 0.0f
                     : (MODE == M_MAX) ? -3.402823466e38f : 3.402823466e38f;
    float acc[8][4];
#pragma unroll
    for (int bb = 0; bb < 8; bb++)
#pragma unroll
        for (int oo = 0; oo < 4; oo++) acc[bb][oo] = init;

    const float* wb = Wm  + (o0 + ro) * Kld + i0 + lo * 4;  // rows ro,+32,+64,+96
    const float* hb = Hin + (b0 + ro) * Kld + i0 + lo * 4;  // rows ro,+32

    float4 wreg[4], hreg[2];
    const int nC = Ki / KC;

    // ---- prologue: chunk 0 -> regs -> buf 0 ----
#pragma unroll
    for (int r = 0; r < 4; r++) wreg[r] = *(const float4*)(wb + r * 32 * Kld);
#pragma unroll
    for (int rr = 0; rr < 2; rr++) hreg[rr] = *(const float4*)(hb + rr * 32 * Kld);
    {
        float* pw = sw;  float* ph = sh;
#pragma unroll
        for (int r = 0; r < 4; r++) {
            const int col = r * 32 + ro;
            pw[(lo * 4 + 0) * WST + col] = wreg[r].x;
            pw[(lo * 4 + 1) * WST + col] = wreg[r].y;
            pw[(lo * 4 + 2) * WST + col] = wreg[r].z;
            pw[(lo * 4 + 3) * WST + col] = wreg[r].w;
        }
#pragma unroll
        for (int rr = 0; rr < 2; rr++) {
            const int col = rr * 32 + ro;
            ph[(lo * 4 + 0) * HST + col] = hreg[rr].x;
            ph[(lo * 4 + 1) * HST + col] = hreg[rr].y;
            ph[(lo * 4 + 2) * HST + col] = hreg[rr].z;
            ph[(lo * 4 + 3) * HST + col] = hreg[rr].w;
        }
    }
    __syncthreads();

    for (int c = 0; c < nC; c++) {
        // prefetch chunk c+1 into regs (overlaps with compute below)
        if (c + 1 < nC) {
            const int ic = (c + 1) * KC;
#pragma unroll
            for (int r = 0; r < 4; r++)
                wreg[r] = *(const float4*)(wb + r * 32 * Kld + ic);
#pragma unroll
            for (int rr = 0; rr < 2; rr++)
                hreg[rr] = *(const float4*)(hb + rr * 32 * Kld + ic);
        }

        // compute from buf c&1
        const float* pw = sw + (c & 1) * SW_SZ;
        const float* ph = sh + (c & 1) * SH_SZ;
#pragma unroll 4
        for (int i = 0; i < KC; i++) {
            const float4 wv = *(const float4*)&pw[i * WST + og * 4];      // conflict-free
            const float4 h0 = *(const float4*)&ph[i * HST + bg * 8];      // broadcast
            const float4 h1 = *(const float4*)&ph[i * HST + bg * 8 + 4];  // broadcast
            const float w4[4] = {wv.x, wv.y, wv.z, wv.w};
            const float h8[8] = {h0.x, h0.y, h0.z, h0.w, h1.x, h1.y, h1.z, h1.w};
#pragma unroll
            for (int bb = 0; bb < 8; bb++)
#pragma unroll
                for (int oo = 0; oo < 4; oo++) {
                    if (MODE == M_FMA)
                        acc[bb][oo] = fmaf(w4[oo], h8[bb], acc[bb][oo]);
                    else if (MODE == M_MAX)
                        acc[bb][oo] = fmaxf(acc[bb][oo], w4[oo] + h8[bb]);
                    else
                        acc[bb][oo] = fminf(acc[bb][oo], w4[oo] + h8[bb]);
                }
        }

        // stage chunk c+1 into the other buffer; single barrier per chunk
        if (c + 1 < nC) {
            float* qw = sw + ((c + 1) & 1) * SW_SZ;
            float* qh = sh + ((c + 1) & 1) * SH_SZ;
#pragma unroll
            for (int r = 0; r < 4; r++) {
                const int col = r * 32 + ro;
                qw[(lo * 4 + 0) * WST + col] = wreg[r].x;
                qw[(lo * 4 + 1) * WST + col] = wreg[r].y;
                qw[(lo * 4 + 2) * WST + col] = wreg[r].z;
                qw[(lo * 4 + 3) * WST + col] = wreg[r].w;
            }
#pragma unroll
            for (int rr = 0; rr < 2; rr++) {
                const int col = rr * 32 + ro;
                qh[(lo * 4 + 0) * HST + col] = hreg[rr].x;
                qh[(lo * 4 + 1) * HST + col] = hreg[rr].y;
                qh[(lo * 4 + 2) * HST + col] = hreg[rr].z;
                qh[(lo * 4 + 3) * HST + col] = hreg[rr].w;
            }
            __syncthreads();
        }
    }

    // epilogue: write partials
    float* pout = part + (blockIdx.z * NB + b0 + bg * 8) * HD + o0 + og * 4;
#pragma unroll
    for (int bb = 0; bb < 8; bb++)
        *(float4*)(pout + bb * HD) =
            make_float4(acc[bb][0], acc[bb][1], acc[bb][2], acc[bb][3]);
}

// Reduce SPLIT partial slices into a dense activation; M_FMA also adds bias[o].
template<int MODE>
__global__ __launch_bounds__(256)
void combine_kernel(const float* __restrict__ part, float* __restrict__ out,
                    const float* __restrict__ bias)
{
    const int idx = blockIdx.x * 256 + threadIdx.x;  // float4 index over NB*HD/4
    const float4* p = (const float4*)part;
    float4 v = p[idx];
#pragma unroll
    for (int s = 1; s < SPLIT; s++) {
        const float4 u = p[idx + s * (NB * HD / 4)];
        if (MODE == M_FMA) {
            v.x += u.x; v.y += u.y; v.z += u.z; v.w += u.w;
        } else if (MODE == M_MAX) {
            v.x = fmaxf(v.x, u.x); v.y = fmaxf(v.y, u.y);
            v.z = fmaxf(v.z, u.z); v.w = fmaxf(v.w, u.w);
        } else {
            v.x = fminf(v.x, u.x); v.y = fminf(v.y, u.y);
            v.z = fminf(v.z, u.z); v.w = fminf(v.w, u.w);
        }
    }
    if (MODE == M_FMA) {
        const float4 b = *(const float4*)(bias + (idx & (HD / 4 - 1)) * 4);
        v.x += b.x; v.y += b.y; v.z += b.z; v.w += b.w;
    }
    ((float4*)out)[idx] = v;
}

// One CTA per batch row b: min-combine SPLIT partials of h3 once into smem,
// then 8 warps compute the 18 dot products.
__global__ __launch_bounds__(256)
void fcout_kernel(const float* __restrict__ hpart, const float* __restrict__ Wout,
                  const float* __restrict__ bout, float* __restrict__ q)
{
    __shared__ float sh[HD];
    const int b    = blockIdx.x;
    const int tid  = threadIdx.x;
    const int wid  = tid >> 5;
    const int lane = tid & 31;

    const float4* hp = (const float4*)hpart + b * (HD / 4) + tid;
    float4 v = hp[0];
#pragma unroll
    for (int z = 1; z < SPLIT; z++) {
        const float4 u = hp[z * (NB * HD / 4)];
        v.x = fminf(v.x, u.x); v.y = fminf(v.y, u.y);
        v.z = fminf(v.z, u.z); v.w = fminf(v.w, u.w);
    }
    ((float4*)sh)[tid] = v;
    __syncthreads();

    for (int a = wid; a < NA; a += 8) {
        const float4* wr = (const float4*)(Wout + a * HD);
        const float4* hs = (const float4*)sh;
        float s = 0.0f;
#pragma unroll
        for (int k = 0; k < HD / 128; k++) {
            const float4 w4 = wr[lane + k * 32];
            const float4 h4 = hs[lane + k * 32];
            s = fmaf(w4.x, h4.x, s);
            s = fmaf(w4.y, h4.y, s);
            s = fmaf(w4.z, h4.z, s);
            s = fmaf(w4.w, h4.w, s);
        }
#pragma unroll
        for (int d = 16; d; d >>= 1) s += __shfl_xor_sync(0xffffffffu, s, d);
        if (lane == 0) q[b * NA + a] = s + bout[a];
    }
}

extern "C" void kernel_launch(void* const* d_in, const int* in_sizes, int n_in,
                              void* d_out, int out_size)
{
    const float* x     = (const float*)d_in[0];
    const float* W_in  = (const float*)d_in[1];
    const float* b_in  = (const float*)d_in[2];
    const float* W_max = (const float*)d_in[3];
    const float* W_min = (const float*)d_in[4];
    const float* W_out = (const float*)d_in[5];
    const float* b_out = (const float*)d_in[6];
    float* q = (float*)d_out;

    float *part, *h1, *h2;
    cudaGetSymbolAddress((void**)&part, g_part);
    cudaGetSymbolAddress((void**)&h1, g_h1);
    cudaGetSymbolAddress((void**)&h2, g_h2);

    // Opt in to >48KB dynamic smem (idempotent; safe under graph capture).
    cudaFuncSetAttribute(semiring_kernel<M_FMA>,
                         cudaFuncAttributeMaxDynamicSharedMemorySize, SMEM_BYTES);
    cudaFuncSetAttribute(semiring_kernel<M_MAX>,
                         cudaFuncAttributeMaxDynamicSharedMemorySize, SMEM_BYTES);
    cudaFuncSetAttribute(semiring_kernel<M_MIN>,
                         cudaFuncAttributeMaxDynamicSharedMemorySize, SMEM_BYTES);

    const dim3 grid(HD / OT, NB / BT, SPLIT);  // (8, 4, 8) = 256 CTAs
    const int  cgrid = NB * HD / 4 / 256;      // 256

    // 1) fc_in partials + combine(sum, +b_in) -> h1
    semiring_kernel<M_FMA><<<grid, NT, SMEM_BYTES>>>(W_in, x, part, NOBS, NOBS / SPLIT);
    combine_kernel<M_FMA><<<cgrid, 256>>>(part, h1, b_in);

    // 2) max-plus partials + combine(max) -> h2
    semiring_kernel<M_MAX><<<grid, NT, SMEM_BYTES>>>(W_max, h1, part, HD, HD / SPLIT);
    combine_kernel<M_MAX><<<cgrid, 256>>>(part, h2, nullptr);

    // 3) min-plus partials (combined inline by fcout)
    semiring_kernel<M_MIN><<<grid, NT, SMEM_BYTES>>>(W_min, h2, part, HD, HD / SPLIT);

    // 4) fc_out: h3 = min_z partials; q = h3 @ W_out^T + b_out
    fcout_kernel<<<NB, 256>>>(part, W_out, b_out, q);
}